// round 17
// baseline (speedup 1.0000x reference)
#include <cuda_runtime.h>
#include <cuda_fp16.h>
#include <cstdint>

// ---------------- problem constants ----------------
#define BB   8
#define NT   2
#define NN   2000
#define ENN  4000
#define NNZE 32000
#define LL   8
#define DD   64
#define LD   512
#define SEG  (BB*NT)
#define NPB  8             // nodes per block -> M = 64
#define NBLK (NN/NPB)      // 250
#define KD   192
#define BCAP 64            // bucket capacity; Poisson(16) => P(>64) ~ 1e-20

// A smem: 64 rows x 200 fp16 slots (400 B/row, 192 used).
#define AROW 200
#define A_BYTES (64 * AROW * 2)      // 25600
#define SMEM_TOTAL A_BYTES

#define STATE_ELEMS ((size_t)BB * ENN * LD)    // 16,384,000 per tensor
#define CONV_PER (int)(STATE_ELEMS / 8)        // 2,048,000 threads per tensor

// ---------------- device scratch ----------------
__device__ int   g_cnt [SEG * NN];            // zero-init; re-zeroed by k_main tail
__device__ int2  g_bkt [(size_t)SEG * NN * BCAP];
__device__ __align__(16) __half g_s16[2 * STATE_ELEMS];   // fp16 state_in | state_out
__device__ __align__(16) __half g_W16[3 * 64 * 192];      // [mat][n][k] fp16

// ---------------- helpers ----------------
__device__ __forceinline__ uint32_t smem_u32(const void* p) {
    uint32_t a;
    asm("{ .reg .u64 t; cvta.to.shared.u64 t, %1; cvt.u32.u64 %0, t; }" : "=r"(a) : "l"(p));
    return a;
}
__device__ __forceinline__ float sigm(float x) { return 1.0f / (1.0f + __expf(-x)); }

#define LDMATRIX_X4(r0, r1, r2, r3, addr) \
    asm volatile("ldmatrix.sync.aligned.m8n8.x4.shared.b16 {%0,%1,%2,%3}, [%4];" \
        : "=r"(r0), "=r"(r1), "=r"(r2), "=r"(r3) : "r"(addr))

#define MMA16816F16(c, a0, a1, a2, a3, b0, b1) \
    asm volatile("mma.sync.aligned.m16n8k16.row.col.f32.f16.f16.f32 " \
        "{%0,%1,%2,%3}, {%4,%5,%6,%7}, {%8,%9}, {%0,%1,%2,%3};" \
        : "+f"((c)[0]), "+f"((c)[1]), "+f"((c)[2]), "+f"((c)[3]) \
        : "r"(a0), "r"(a1), "r"(a2), "r"(a3), "r"(b0), "r"(b1))

// fp16-row FMA: 8 halves (one uint4) scaled into 8 fp32 accumulators
__device__ __forceinline__ void fma8(float* a, const uint4& p, float v) {
    const __half2* h = reinterpret_cast<const __half2*>(&p);
#pragma unroll
    for (int q = 0; q < 4; ++q) {
        float2 f = __half22float2(h[q]);
        a[2 * q]     += v * f.x;
        a[2 * q + 1] += v * f.y;
    }
}
// pack 8 fp32 -> fp16 uint4
__device__ __forceinline__ uint4 pack8(const float* a) {
    uint4 o;
    uint32_t* p = reinterpret_cast<uint32_t*>(&o);
#pragma unroll
    for (int q = 0; q < 4; ++q) {
        __half2 h = __floats2half2_rn(a[2 * q], a[2 * q + 1]);
        p[q] = *reinterpret_cast<uint32_t*>(&h);
    }
    return o;
}

// ---------------- scatter + fp16 state conversion + W prep (one launch) ----------------
// g_cnt is zero on entry (static init / re-zeroed by previous k_main).
__global__ void k_scatter(const float* __restrict__ vals,
                          const int*   __restrict__ rows,
                          const int*   __restrict__ cols,
                          const float* __restrict__ state_in,
                          const float* __restrict__ state_out,
                          const float* __restrict__ Wr,
                          const float* __restrict__ Wz,
                          const float* __restrict__ Wh) {
    int idx = blockIdx.x * blockDim.x + threadIdx.x;
    // fp16 state conversion: 8 elems per thread
    if (idx < 2 * CONV_PER) {
        const bool second = (idx >= CONV_PER);
        const float* src = second ? state_out : state_in;
        const size_t base = (size_t)(second ? idx - CONV_PER : idx) * 8;
        __half* dst = g_s16 + (second ? STATE_ELEMS : 0) + base;
        float4 x0 = __ldg(reinterpret_cast<const float4*>(src + base));
        float4 x1 = __ldg(reinterpret_cast<const float4*>(src + base) + 1);
        uint4 o;
        __half2 h;
        h = __floats2half2_rn(x0.x, x0.y); o.x = *reinterpret_cast<uint32_t*>(&h);
        h = __floats2half2_rn(x0.z, x0.w); o.y = *reinterpret_cast<uint32_t*>(&h);
        h = __floats2half2_rn(x1.x, x1.y); o.z = *reinterpret_cast<uint32_t*>(&h);
        h = __floats2half2_rn(x1.z, x1.w); o.w = *reinterpret_cast<uint32_t*>(&h);
        *reinterpret_cast<uint4*>(dst) = o;
    }
    // W prep
    if (idx < 3 * 64 * 192) {
        int mat = idx / (64 * 192);
        int r   = idx - mat * (64 * 192);
        const float* W = (mat == 0) ? Wr : (mat == 1) ? Wz : Wh;
        g_W16[idx] = __float2half(W[r]);
    }
    // edge scatter
    if (idx < SEG * NNZE) {
        int seg = idx / NNZE;
        int slot = seg * NN + rows[idx];
        int pos = atomicAdd(&g_cnt[slot], 1);
        if (pos < BCAP)
            g_bkt[(size_t)slot * BCAP + pos] = make_int2(__float_as_int(vals[idx]), cols[idx]);
    }
}

// ---------------- main fused kernel ----------------
__global__ void __launch_bounds__(256, 3)
k_main(const float* __restrict__ state_cur,
       const float* __restrict__ b_r,
       const float* __restrict__ b_z,
       const float* __restrict__ b_h,
       float* __restrict__ out) {
    extern __shared__ char smem[];
    __half* As = reinterpret_cast<__half*>(smem);
    const uint32_t sbh = smem_u32(smem);

    const int tid  = threadIdx.x;
    const int w    = tid >> 5;
    const int lane = tid & 31;
    const int b    = blockIdx.x / NBLK;
    const int nb   = (blockIdx.x - b * NBLK) * NPB;

    // ---------- Phase 1: SpMM gather over fp16 state, 4-edge groups (MLP=8) ----------
    for (int task = w; task < 16; task += 8) {
        const int node = task >> 1;
        const int type = task & 1;
        const int n    = nb + node;
        const int seg  = b * NT + type;
        const int slot = seg * NN + n;
        const __half* S = g_s16 + (type ? STATE_ELEMS : 0) + (size_t)b * ENN * LD;
        const int2*  E  = g_bkt + (size_t)slot * BCAP;
        int rem = g_cnt[slot];
        if (rem > BCAP) rem = BCAP;

        float acc0[8], acc1[8];
#pragma unroll
        for (int q = 0; q < 8; ++q) { acc0[q] = 0.0f; acc1[q] = 0.0f; }

        if (rem > 0) {
            float v[4];
            uint4 p0[4], p1[4];
#pragma unroll
            for (int j = 0; j < 4; ++j) {
                const int ij = (j < rem) ? j : (rem - 1);
                int2 e = __ldg(&E[ij]);
                v[j] = (j < rem) ? __int_as_float(e.x) : 0.0f;
                const uint4* rp = reinterpret_cast<const uint4*>(S + (size_t)e.y * LD);
                p0[j] = __ldg(rp + lane);
                p1[j] = __ldg(rp + 32 + lane);
            }
            for (int i = 0; i < rem; i += 4) {
                float nv[4];
                int   nc[4];
#pragma unroll
                for (int j = 0; j < 4; ++j) {
                    const int gj = i + 4 + j;
                    const int ij = (gj < rem) ? gj : (rem - 1);
                    int2 e = __ldg(&E[ij]);
                    nv[j] = (gj < rem) ? __int_as_float(e.x) : 0.0f;
                    nc[j] = e.y;
                }
#pragma unroll
                for (int j = 0; j < 4; ++j) {
                    fma8(acc0, p0[j], v[j]);
                    fma8(acc1, p1[j], v[j]);
                }
#pragma unroll
                for (int j = 0; j < 4; ++j) {
                    const uint4* rp = reinterpret_cast<const uint4*>(S + (size_t)nc[j] * LD);
                    p0[j] = __ldg(rp + lane);
                    p1[j] = __ldg(rp + 32 + lane);
                    v[j]  = nv[j];
                }
            }
        }

        // acc0 -> row l = lane>>3, cols [(lane&7)*8, +8); acc1 -> row +4
        const int l0 = lane >> 3;
        const int d0 = (lane & 7) * 8;
        const int kb = type * DD + d0;
        {
            const int row = node * LL + l0;
            *reinterpret_cast<uint4*>(&As[row * AROW + kb]) = pack8(acc0);
        }
        {
            const int row = node * LL + 4 + l0;
            *reinterpret_cast<uint4*>(&As[row * AROW + kb]) = pack8(acc1);
        }
    }
    // state_cur (fp32): warp w loads node w
    {
        const int n = nb + w;
        const float4* C = reinterpret_cast<const float4*>(state_cur + (size_t)(b * NN + n) * LD);
#pragma unroll
        for (int j = 0; j < 4; ++j) {
            const int Eidx = j * 32 + lane;
            const int l    = Eidx >> 4;
            const int d4   = (Eidx & 15) * 4;
            float4 vx = __ldg(C + Eidx);
            const int row = w * LL + l;
            const int kb  = 128 + d4;
            __half2 h01 = __floats2half2_rn(vx.x, vx.y);
            __half2 h23 = __floats2half2_rn(vx.z, vx.w);
            uint2 hw;
            hw.x = *reinterpret_cast<uint32_t*>(&h01);
            hw.y = *reinterpret_cast<uint32_t*>(&h23);
            *reinterpret_cast<uint2*>(&As[row * AROW + kb]) = hw;
        }
    }
    __syncthreads();   // ALL warps have read their g_cnt slots before this point

    // re-zero this block's 16 g_cnt slots for the next graph replay
    if (tid < 16) {
        const int node = tid >> 1;
        const int type = tid & 1;
        g_cnt[(b * NT + type) * NN + nb + node] = 0;
    }

    // ---------- Phase 2: fp16 HMMA GEMMs (single term) ----------
    const int n0 = w * 8;
    const int qr = lane >> 2;
    const int qc = (lane & 3) * 2;

    float cr[16], cz[16], ch[16];
#pragma unroll
    for (int i = 0; i < 16; ++i) { cr[i] = 0.0f; cz[i] = 0.0f; ch[i] = 0.0f; }

    const int arow = lane & 15;
    const int koff16 = ((lane >> 4) & 1) * 16;
    const int bnr = (n0 + qr) * 192 + qc;

#pragma unroll
    for (int kt = 0; kt < 8; ++kt) {
        const int k0 = kt * 16;
        const uint32_t br0 = *reinterpret_cast<const uint32_t*>(g_W16 + bnr + k0);
        const uint32_t br1 = *reinterpret_cast<const uint32_t*>(g_W16 + bnr + k0 + 8);
        const uint32_t bz0 = *reinterpret_cast<const uint32_t*>(g_W16 + 64*192 + bnr + k0);
        const uint32_t bz1 = *reinterpret_cast<const uint32_t*>(g_W16 + 64*192 + bnr + k0 + 8);
        const uint32_t bh0 = *reinterpret_cast<const uint32_t*>(g_W16 + 128*192 + bnr + k0);
        const uint32_t bh1 = *reinterpret_cast<const uint32_t*>(g_W16 + 128*192 + bnr + k0 + 8);
#pragma unroll
        for (int i = 0; i < 4; ++i) {
            const uint32_t aoff = (uint32_t)((16 * i + arow) * 400 + k0 * 2 + koff16);
            uint32_t a0, a1, a2, a3;
            LDMATRIX_X4(a0, a1, a2, a3, sbh + aoff);
            MMA16816F16(cr + 4*i, a0, a1, a2, a3, br0, br1);
            MMA16816F16(cz + 4*i, a0, a1, a2, a3, bz0, bz1);
            MMA16816F16(ch + 4*i, a0, a1, a2, a3, bh0, bh1);
        }
    }
#pragma unroll
    for (int kt = 8; kt < 12; ++kt) {
        const int k0 = kt * 16;
        const uint32_t br0 = *reinterpret_cast<const uint32_t*>(g_W16 + bnr + k0);
        const uint32_t br1 = *reinterpret_cast<const uint32_t*>(g_W16 + bnr + k0 + 8);
        const uint32_t bz0 = *reinterpret_cast<const uint32_t*>(g_W16 + 64*192 + bnr + k0);
        const uint32_t bz1 = *reinterpret_cast<const uint32_t*>(g_W16 + 64*192 + bnr + k0 + 8);
#pragma unroll
        for (int i = 0; i < 4; ++i) {
            const uint32_t aoff = (uint32_t)((16 * i + arow) * 400 + k0 * 2 + koff16);
            uint32_t a0, a1, a2, a3;
            LDMATRIX_X4(a0, a1, a2, a3, sbh + aoff);
            MMA16816F16(cr + 4*i, a0, a1, a2, a3, br0, br1);
            MMA16816F16(cz + 4*i, a0, a1, a2, a3, bz0, bz1);
        }
    }
    __syncthreads();

    // ---------- Epilogue 1: r, z; write rc = r*cur over cur columns ----------
    float curv[16], zreg[16];
#pragma unroll
    for (int i = 0; i < 4; ++i) {
#pragma unroll
        for (int rr = 0; rr < 2; ++rr) {
            const int m = 16 * i + qr + 8 * rr;
#pragma unroll
            for (int cc = 0; cc < 2; ++cc) {
                const int o   = n0 + qc + cc;
                const int idx = i * 4 + rr * 2 + cc;
                const int e   = m * AROW + 128 + o;
                const float cur = __half2float(As[e]);
                curv[idx] = cur;
                const float rv = sigm(cr[idx] + __ldg(&b_r[o]));
                zreg[idx] = sigm(cz[idx] + __ldg(&b_z[o]));
                As[e] = __float2half(rv * cur);
            }
        }
    }
    __syncthreads();

    // ---------- Phase 3: finish h with rc columns ----------
#pragma unroll
    for (int kt = 8; kt < 12; ++kt) {
        const int k0 = kt * 16;
        const uint32_t bh0 = *reinterpret_cast<const uint32_t*>(g_W16 + 128*192 + bnr + k0);
        const uint32_t bh1 = *reinterpret_cast<const uint32_t*>(g_W16 + 128*192 + bnr + k0 + 8);
#pragma unroll
        for (int i = 0; i < 4; ++i) {
            const uint32_t aoff = (uint32_t)((16 * i + arow) * 400 + k0 * 2 + koff16);
            uint32_t a0, a1, a2, a3;
            LDMATRIX_X4(a0, a1, a2, a3, sbh + aoff);
            MMA16816F16(ch + 4*i, a0, a1, a2, a3, bh0, bh1);
        }
    }

    // ---------- Epilogue 2: GRU combine + store ----------
#pragma unroll
    for (int i = 0; i < 4; ++i) {
#pragma unroll
        for (int rr = 0; rr < 2; ++rr) {
            const int m    = 16 * i + qr + 8 * rr;
            const int node = m >> 3;
            const int l    = m & 7;
            const size_t grow = ((size_t)(b * NN + nb + node) * LL + l);
            float2 v;
#pragma unroll
            for (int cc = 0; cc < 2; ++cc) {
                const int o   = n0 + qc + cc;
                const int idx = i * 4 + rr * 2 + cc;
                const float h = tanhf(ch[idx] + __ldg(&b_h[o]));
                const float z = zreg[idx];
                const float r2 = (1.0f - z) * curv[idx] + z * h;
                if (cc == 0) v.x = r2; else v.y = r2;
            }
            *reinterpret_cast<float2*>(out + grow * DD + n0 + qc) = v;
        }
    }
}

// ---------------- launch ----------------
extern "C" void kernel_launch(void* const* d_in, const int* in_sizes, int n_in,
                              void* d_out, int out_size) {
    (void)in_sizes; (void)n_in; (void)out_size;
    const float* state_in  = (const float*)d_in[0];
    const float* state_out = (const float*)d_in[1];
    const float* state_cur = (const float*)d_in[2];
    const float* A_vals    = (const float*)d_in[3];
    const int*   A_rows    = (const int*)  d_in[4];
    const int*   A_cols    = (const int*)  d_in[5];
    const float* W_r       = (const float*)d_in[6];
    const float* b_r       = (const float*)d_in[7];
    const float* W_z       = (const float*)d_in[8];
    const float* b_z       = (const float*)d_in[9];
    const float* W_h       = (const float*)d_in[10];
    const float* b_h       = (const float*)d_in[11];
    float* out = (float*)d_out;

    cudaFuncSetAttribute(k_main, cudaFuncAttributeMaxDynamicSharedMemorySize, SMEM_TOTAL);

    k_scatter<<<(2 * CONV_PER + 255) / 256, 256>>>(A_vals, A_rows, A_cols,
                                                   state_in, state_out, W_r, W_z, W_h);
    k_main<<<BB * NBLK, 256, SMEM_TOTAL>>>(state_cur, b_r, b_z, b_h, out);
}